// round 13
// baseline (speedup 1.0000x reference)
#include <cuda_runtime.h>

// Problem constants
#define BB 2
#define CC 128
#define GG 8
#define CG 16
#define HH 64
#define WW 64

// Attention tile: 16x16, trimmed halo (corners of the 30x30 halo are unused)
#define TT 16
#define NSLOT 740                 // exact access-union slot count
#define KVF (NSLOT*CG)            // floats per map in smem = 11840
#define SMEM_FLOATS (2*KVF + 32 + 112)
#define SMEM_BYTES (SMEM_FLOATS*4)   // ~95.3 KB -> 2 blocks/SM -> 16 warps

#define L2E 1.4426950408889634f

// Transposed scratch: [b][g][h][w][c], 16-ch contiguous (64B)
__device__ float g_q[BB*GG*HH*WW*CG];
__device__ float g_k[BB*GG*HH*WW*CG];
__device__ float g_v[BB*GG*HH*WW*CG];

typedef unsigned long long ull;
__device__ __forceinline__ ull pk2(float lo, float hi) {
    ull r; asm("mov.b64 %0, {%1, %2};" : "=l"(r) : "f"(lo), "f"(hi)); return r;
}
__device__ __forceinline__ void upk2(ull v, float& lo, float& hi) {
    asm("mov.b64 {%0, %1}, %2;" : "=f"(lo), "=f"(hi) : "l"(v));
}
__device__ __forceinline__ void fma2(ull& d, ull a, ull b) {
    asm("fma.rn.f32x2 %0, %1, %2, %0;" : "+l"(d) : "l"(a), "l"(b));
}
__device__ __forceinline__ void mul2(ull& d, ull a, ull b) {
    asm("mul.rn.f32x2 %0, %1, %2;" : "=l"(d) : "l"(a), "l"(b));
}
__device__ __forceinline__ ull add2(ull a, ull b) {
    ull r; asm("add.rn.f32x2 %0, %1, %2;" : "=l"(r) : "l"(a), "l"(b)); return r;
}
__device__ __forceinline__ float ex2(float x) {
    float r; asm("ex2.approx.f32 %0, %1;" : "=f"(r) : "f"(x)); return r;
}

// ---------------------------------------------------------------------------
// Kernel 1: fused Q/K/V 1x1 conv GEMM. grid.z: 0 = Q (from fm[:,128:]),
// 1 = K+V fused (share activation tile). 256 thr, 64 px x 128 oc per block.
// ---------------------------------------------------------------------------
__global__ __launch_bounds__(256) void qkv_gemm(
    const float* __restrict__ fm,
    const float* __restrict__ wq,
    const float* __restrict__ wk,
    const float* __restrict__ wv)
{
    __shared__ float wS[128][33];    // K or Q weights [oc][kk]
    __shared__ float wS2[128][33];   // V weights (z==1 only)
    __shared__ float xS[32][64];     // [kk][pixel]

    int z    = blockIdx.z;
    int t    = threadIdx.x;
    int pix0 = blockIdx.x * 64;
    int b    = pix0 >> 12;
    int rem0 = pix0 & 4095;

    int ocb = (t >> 4) << 3;               // 0..120 step 8
    int pxb = (t & 15) << 2;               // 0..60 step 4
    int g   = ocb >> 4;
    int c0  = ocb & 15;

    if (z == 0) {
        // ---------------- Q path ----------------
        const float* xbase = fm + ((size_t)(b * 256 + 128) << 12) + rem0;
        float acc[8][4];
#pragma unroll
        for (int u = 0; u < 8; u++)
#pragma unroll
            for (int p = 0; p < 4; p++) acc[u][p] = 0.f;

        for (int ic0 = 0; ic0 < 128; ic0 += 32) {
#pragma unroll
            for (int j = 0; j < 16; j++) {
                int idx = t + j * 256;
                wS[idx >> 5][idx & 31] = wq[(idx >> 5) * 128 + ic0 + (idx & 31)];
            }
#pragma unroll
            for (int j = 0; j < 8; j++) {
                int idx = t + j * 256;
                xS[idx >> 6][idx & 63] =
                    xbase[(size_t)(ic0 + (idx >> 6)) * 4096 + (idx & 63)];
            }
            __syncthreads();
#pragma unroll
            for (int kk = 0; kk < 32; kk++) {
                float x0 = xS[kk][pxb + 0], x1 = xS[kk][pxb + 1];
                float x2 = xS[kk][pxb + 2], x3 = xS[kk][pxb + 3];
#pragma unroll
                for (int u = 0; u < 8; u++) {
                    float wv_ = wS[ocb + u][kk];
                    acc[u][0] += wv_ * x0; acc[u][1] += wv_ * x1;
                    acc[u][2] += wv_ * x2; acc[u][3] += wv_ * x3;
                }
            }
            __syncthreads();
        }
#pragma unroll
        for (int p = 0; p < 4; p++) {
            int pix = rem0 + pxb + p;
            int h = pix >> 6, ww_ = pix & 63;
            size_t base = ((size_t)((b * GG + g) * HH + h) * WW + ww_) * CG + c0;
            *(float4*)(g_q + base)     = make_float4(acc[0][p], acc[1][p], acc[2][p], acc[3][p]);
            *(float4*)(g_q + base + 4) = make_float4(acc[4][p], acc[5][p], acc[6][p], acc[7][p]);
        }
    } else {
        // ---------------- fused K + V path ----------------
        const float* xbase = fm + ((size_t)(b * 256) << 12) + rem0;
        float aK[8][4], aV[8][4];
#pragma unroll
        for (int u = 0; u < 8; u++)
#pragma unroll
            for (int p = 0; p < 4; p++) { aK[u][p] = 0.f; aV[u][p] = 0.f; }

        for (int ic0 = 0; ic0 < 128; ic0 += 32) {
#pragma unroll
            for (int j = 0; j < 16; j++) {
                int idx = t + j * 256;
                wS [idx >> 5][idx & 31] = wk[(idx >> 5) * 128 + ic0 + (idx & 31)];
                wS2[idx >> 5][idx & 31] = wv[(idx >> 5) * 128 + ic0 + (idx & 31)];
            }
#pragma unroll
            for (int j = 0; j < 8; j++) {
                int idx = t + j * 256;
                xS[idx >> 6][idx & 63] =
                    xbase[(size_t)(ic0 + (idx >> 6)) * 4096 + (idx & 63)];
            }
            __syncthreads();
#pragma unroll
            for (int kk = 0; kk < 32; kk++) {
                float x0 = xS[kk][pxb + 0], x1 = xS[kk][pxb + 1];
                float x2 = xS[kk][pxb + 2], x3 = xS[kk][pxb + 3];
#pragma unroll
                for (int u = 0; u < 8; u++) {
                    float wkv = wS[ocb + u][kk];
                    aK[u][0] += wkv * x0; aK[u][1] += wkv * x1;
                    aK[u][2] += wkv * x2; aK[u][3] += wkv * x3;
                    float wvv = wS2[ocb + u][kk];
                    aV[u][0] += wvv * x0; aV[u][1] += wvv * x1;
                    aV[u][2] += wvv * x2; aV[u][3] += wvv * x3;
                }
            }
            __syncthreads();
        }
#pragma unroll
        for (int p = 0; p < 4; p++) {
            int pix = rem0 + pxb + p;
            int h = pix >> 6, ww_ = pix & 63;
            size_t base = ((size_t)((b * GG + g) * HH + h) * WW + ww_) * CG + c0;
            *(float4*)(g_k + base)     = make_float4(aK[0][p], aK[1][p], aK[2][p], aK[3][p]);
            *(float4*)(g_k + base + 4) = make_float4(aK[4][p], aK[5][p], aK[6][p], aK[7][p]);
            *(float4*)(g_v + base)     = make_float4(aV[0][p], aV[1][p], aV[2][p], aV[3][p]);
            *(float4*)(g_v + base + 4) = make_float4(aV[4][p], aV[5][p], aV[6][p], aV[7][p]);
        }
    }
}

// ---------------------------------------------------------------------------
// Kernel 2: fused windowed attention. 16x16 tile, 256 threads, 1 thread/px.
// Trimmed 740-slot halo in quad-plane layout (conflict-free LDS.128, no pad).
// Variable-width rows addressed via 30-entry LUT: slot = lut[r+7] + c.
//   rows -7..-4 : cols [0,15]   (16 wide)  base 0    (col strip only)
//   rows -3..-1 : cols [-3,18]  (22 wide)  base 64
//   rows  0..15 : cols [-7,22]  (30 wide)  base 130
//   rows 16..18 : cols [-3,18]  (22 wide)  base 610
//   rows 19..22 : cols [0,15]   (16 wide)  base 676
// ---------------------------------------------------------------------------
__global__ __launch_bounds__(256, 2) void attn_kernel(
    const float* __restrict__ relh,
    const float* __restrict__ relw,
    float* __restrict__ out)
{
    extern __shared__ float sh[];
    float* Ks   = sh;                     // 4 planes x 740 x 4 floats
    float* Vs   = sh + KVF;
    int*   lutS = (int*)(sh + 2 * KVF);   // 32 ints
    float* relS = sh + 2 * KVF + 32;      // 112 floats

    int tid = threadIdx.x;
    int bz  = blockIdx.z;
    int b   = bz >> 3;
    int g   = bz & 7;
    int h0  = blockIdx.y * TT;
    int w0  = blockIdx.x * TT;

    const float* Kg = g_k + (size_t)(b * GG + g) * (HH * WW * CG);
    const float* Vg = g_v + (size_t)(b * GG + g) * (HH * WW * CG);

    // Row-base LUT (already shifted so slot = lut[r+7] + c, c = global-rel col)
    if (tid < 30) {
        int r = tid - 7;
        int v;
        if (r < -3)      v = (r + 7) * 16;
        else if (r < 0)  v = 64  + (r + 3) * 22 + 3;
        else if (r < 16) v = 130 + r * 30 + 7;
        else if (r < 19) v = 610 + (r - 16) * 22 + 3;
        else             v = 676 + (r - 19) * 16;
        lutS[tid] = v;
    }
    if (tid < 112)
        relS[tid] = (g < 4) ? relh[g * 112 + tid] : relw[(g - 4) * 112 + tid];

    // Halo fill: decode compact slot -> (r, c), zero-fill OOB
    for (int idx = tid; idx < NSLOT * 4; idx += 256) {
        int s = idx >> 2, q = idx & 3;
        int r, c;
        if (s < 64)       { r = -7 + (s >> 4);           c = s & 15; }
        else if (s < 130) { int t2 = s - 64;  int rr = t2 / 22; r = -3 + rr; c = t2 - rr * 22 - 3; }
        else if (s < 610) { int t2 = s - 130; int rr = t2 / 30; r = rr;      c = t2 - rr * 30 - 7; }
        else if (s < 676) { int t2 = s - 610; int rr = t2 / 22; r = 16 + rr; c = t2 - rr * 22 - 3; }
        else              { int t2 = s - 676; r = 19 + (t2 >> 4); c = t2 & 15; }
        int gh = h0 + r, gw = w0 + c;
        float4 kv = make_float4(0.f, 0.f, 0.f, 0.f);
        float4 vv = kv;
        if ((unsigned)gh < HH && (unsigned)gw < WW) {
            size_t off = (size_t)((gh << 6) + gw) * CG + (q << 2);
            kv = *(const float4*)(Kg + off);
            vv = *(const float4*)(Vg + off);
        }
        *(float4*)(Ks + (q * NSLOT + s) * 4) = kv;
        *(float4*)(Vs + (q * NSLOT + s) * 4) = vv;
    }
    __syncthreads();

    int row = tid >> 4, col = tid & 15;
    int h = h0 + row, w = w0 + col;

    // q (16 ch), pre-scaled by log2(e)
    const float* qp = g_q + ((size_t)((b * GG + g) * HH + h) * WW + w) * CG;
    float qs[16];
#pragma unroll
    for (int i = 0; i < 4; i++) {
        float4 qf = *(const float4*)(qp + i * 4);
        qs[i*4+0] = qf.x * L2E; qs[i*4+1] = qf.y * L2E;
        qs[i*4+2] = qf.z * L2E; qs[i*4+3] = qf.w * L2E;
    }

    float bias[7];
#pragma unroll
    for (int i = 0; i < 7; i++) {
        float bsum = 0.f;
#pragma unroll
        for (int cc = 0; cc < 16; cc++)
            bsum = fmaf(qs[cc], relS[cc * 7 + i], bsum);
        bias[i] = bsum;
    }

    ull q2[8];
#pragma unroll
    for (int i = 0; i < 8; i++) q2[i] = pk2(qs[2*i], qs[2*i+1]);

    bool gh4 = (g < 4);

    // ---- Main 7x7 window ----
    float s0 = 0.f, s1 = 0.f;
    ull o[8];
#pragma unroll
    for (int i = 0; i < 8; i++) o[i] = pk2(0.f, 0.f);

#pragma unroll
    for (int di = 0; di < 7; di++) {
        int sb = lutS[row + 4 + di] + (col - 3);
#pragma unroll
        for (int dj = 0; dj < 7; dj++) {
            int sl = sb + dj;
            const float* kp = Ks + sl * 4;
            ulonglong2 k0 = *(const ulonglong2*)(kp);
            ulonglong2 k1 = *(const ulonglong2*)(kp + 1*NSLOT*4);
            ulonglong2 k2 = *(const ulonglong2*)(kp + 2*NSLOT*4);
            ulonglong2 k3 = *(const ulonglong2*)(kp + 3*NSLOT*4);
            float bb = gh4 ? bias[di] : bias[dj];
            ull a0 = pk2(bb, 0.f), a1 = pk2(0.f, 0.f);
            fma2(a0, q2[0], k0.x); fma2(a1, q2[1], k0.y);
            fma2(a0, q2[2], k1.x); fma2(a1, q2[3], k1.y);
            fma2(a0, q2[4], k2.x); fma2(a1, q2[5], k2.y);
            fma2(a0, q2[6], k3.x); fma2(a1, q2[7], k3.y);
            float lo, hi; upk2(add2(a0, a1), lo, hi);
            float e = ex2(lo + hi);
            if (dj & 1) s1 += e; else s0 += e;
            ull ep = pk2(e, e);
            const float* vp = Vs + sl * 4;
            ulonglong2 v0 = *(const ulonglong2*)(vp);
            ulonglong2 v1 = *(const ulonglong2*)(vp + 1*NSLOT*4);
            ulonglong2 v2 = *(const ulonglong2*)(vp + 2*NSLOT*4);
            ulonglong2 v3 = *(const ulonglong2*)(vp + 3*NSLOT*4);
            fma2(o[0], ep, v0.x); fma2(o[1], ep, v0.y);
            fma2(o[2], ep, v1.x); fma2(o[3], ep, v1.y);
            fma2(o[4], ep, v2.x); fma2(o[5], ep, v2.y);
            fma2(o[6], ep, v3.x); fma2(o[7], ep, v3.y);
        }
    }
    {
        float inv = 1.f / (s0 + s1);
        ull ip = pk2(inv, inv);
#pragma unroll
        for (int i = 0; i < 8; i++) mul2(o[i], o[i], ip);
    }

    // ---- Refine passes: row (h fixed) then col (w fixed), no bias ----
#pragma unroll
    for (int pass = 0; pass < 2; pass++) {
        float sr = 0.f;
        ull r8[8];
#pragma unroll
        for (int i = 0; i < 8; i++) r8[i] = pk2(0.f, 0.f);
        int rowBase = lutS[row + 7] + (col - 7);   // row pass slots: +j
#pragma unroll
        for (int j = 0; j < 15; j++) {
            int sl = (pass == 0) ? (rowBase + j) : (lutS[row + j] + col);
            const float* kp = Ks + sl * 4;
            ulonglong2 k0 = *(const ulonglong2*)(kp);
            ulonglong2 k1 = *(const ulonglong2*)(kp + 1*NSLOT*4);
            ulonglong2 k2 = *(const ulonglong2*)(kp + 2*NSLOT*4);
            ulonglong2 k3 = *(const ulonglong2*)(kp + 3*NSLOT*4);
            ull a0 = pk2(0.f, 0.f), a1 = a0;
            fma2(a0, q2[0], k0.x); fma2(a1, q2[1], k0.y);
            fma2(a0, q2[2], k1.x); fma2(a1, q2[3], k1.y);
            fma2(a0, q2[4], k2.x); fma2(a1, q2[5], k2.y);
            fma2(a0, q2[6], k3.x); fma2(a1, q2[7], k3.y);
            float lo, hi; upk2(add2(a0, a1), lo, hi);
            float e = ex2(lo + hi);
            sr += e;
            ull ep = pk2(e, e);
            const float* vp = Vs + sl * 4;
            ulonglong2 v0 = *(const ulonglong2*)(vp);
            ulonglong2 v1 = *(const ulonglong2*)(vp + 1*NSLOT*4);
            ulonglong2 v2 = *(const ulonglong2*)(vp + 2*NSLOT*4);
            ulonglong2 v3 = *(const ulonglong2*)(vp + 3*NSLOT*4);
            fma2(r8[0], ep, v0.x); fma2(r8[1], ep, v0.y);
            fma2(r8[2], ep, v1.x); fma2(r8[3], ep, v1.y);
            fma2(r8[4], ep, v2.x); fma2(r8[5], ep, v2.y);
            fma2(r8[6], ep, v3.x); fma2(r8[7], ep, v3.y);
        }
        float ir = 1.f / sr;
        ull ip = pk2(ir, ir);
#pragma unroll
        for (int i = 0; i < 8; i++) fma2(o[i], ip, r8[i]);
    }

    // Output: standard [b][oc][h][w]
    size_t ob = ((size_t)(b * CC + g * CG) << 12) + (h << 6) + w;
#pragma unroll
    for (int i = 0; i < 8; i++) {
        float lo, hi; upk2(o[i], lo, hi);
        out[ob + (size_t)(2*i)     * 4096] = lo;
        out[ob + (size_t)(2*i + 1) * 4096] = hi;
    }
}

// ---------------------------------------------------------------------------
extern "C" void kernel_launch(void* const* d_in, const int* in_sizes, int n_in,
                              void* d_out, int out_size)
{
    const float* fm = (const float*)d_in[0];
    const float* wq = (const float*)d_in[1];
    const float* wk = (const float*)d_in[2];
    const float* wv = (const float*)d_in[3];
    const float* rh = (const float*)d_in[4];
    const float* rw = (const float*)d_in[5];
    float* out = (float*)d_out;

    cudaFuncSetAttribute(attn_kernel,
                         cudaFuncAttributeMaxDynamicSharedMemorySize, SMEM_BYTES);

    dim3 g1(128, 1, 2);                    // z=0: Q, z=1: fused K+V
    qkv_gemm<<<g1, 256>>>(fm, wq, wk, wv);

    dim3 g2(WW / TT, HH / TT, BB * GG);    // (4, 4, 16) = 256 blocks, 1 wave
    attn_kernel<<<g2, 256, SMEM_BYTES>>>(rh, rw, out);
}